// round 4
// baseline (speedup 1.0000x reference)
#include <cuda_runtime.h>
#include <cstdint>

#define Bz 8
#define Sq 1024
#define Ed 768
#define Hh 12
#define Dd 64
#define N3 2304
#define TOPK 409
#define QT 16
#define KTT 128      // K/V tile rows per pipeline stage
#define KVP 68       // padded row stride (words): lane stride 272B == 16 mod 128 -> conflict-free

// ---- scratch (allocation-free rule: __device__ globals) ----
__device__ float g_Q[Bz*Hh*Sq*Dd];   // [b,h,s,d]
__device__ float g_K[Bz*Hh*Sq*Dd];
__device__ float g_V[Bz*Hh*Sq*Dd];
__device__ float g_AO[Bz*Sq*Ed];     // attention out, [b,s,h,d] = [8192, 768]

// ---- cp.async helpers ----
__device__ __forceinline__ void cp16(void* smem_dst, const void* gmem_src) {
    unsigned s = (unsigned)__cvta_generic_to_shared(smem_dst);
    asm volatile("cp.async.cg.shared.global [%0], [%1], 16;" :: "r"(s), "l"(gmem_src));
}
__device__ __forceinline__ void cp_commit() { asm volatile("cp.async.commit_group;"); }
template<int N>
__device__ __forceinline__ void cp_wait() { asm volatile("cp.async.wait_group %0;" :: "n"(N)); }

// ============================================================
// GEMM: out = A[M,K=768] @ W[768,NDIM] + bias. 128x128x16 tile,
// 256 thr, 8x8/thread, cp.async double-buffered.
// SCATTER=true  -> A = A_in (harness ptr), scatter into g_Q/g_K/g_V
// SCATTER=false -> A = g_AO (device-side symbol!), write to out
// ============================================================
template<int NDIM, bool SCATTER>
__global__ __launch_bounds__(256) void gemm128(const float* __restrict__ A_in,
                                               const float* __restrict__ W,
                                               const float* __restrict__ bias,
                                               float* __restrict__ out) {
    // CRITICAL: __device__ symbol must be resolved in device code, not host.
    const float* A = SCATTER ? A_in : (const float*)g_AO;

    __shared__ float As[2][128*16];   // row-major [m][k]
    __shared__ float Bs[2][16*128];   // [k][n]
    const int t  = threadIdx.x;
    const int tx = t & 15, ty = t >> 4;
    const int m0 = blockIdx.y * 128, n0 = blockIdx.x * 128;

    auto issue = [&](int buf, int k0) {
        #pragma unroll
        for (int i = 0; i < 2; i++) {
            int f = t + 256*i;
            int m = f >> 2, kc = (f & 3) << 2;
            cp16(&As[buf][m*16 + kc], &A[(size_t)(m0 + m)*Ed + k0 + kc]);
        }
        #pragma unroll
        for (int i = 0; i < 2; i++) {
            int f = t + 256*i;
            int kr = f >> 5, nc = (f & 31) << 2;
            cp16(&Bs[buf][kr*128 + nc], &W[(size_t)(k0 + kr)*NDIM + n0 + nc]);
        }
        cp_commit();
    };

    float acc[8][8];
    #pragma unroll
    for (int i = 0; i < 8; i++)
        #pragma unroll
        for (int j = 0; j < 8; j++) acc[i][j] = 0.f;

    issue(0, 0);
    const int NT = Ed / 16;  // 48
    for (int kt = 0; kt < NT; kt++) {
        if (kt + 1 < NT) { issue((kt + 1) & 1, (kt + 1) * 16); cp_wait<1>(); }
        else             { cp_wait<0>(); }
        __syncthreads();
        const float* as = As[kt & 1];
        const float* bs = Bs[kt & 1];
        #pragma unroll
        for (int kk = 0; kk < 16; kk++) {
            float a[8], b[8];
            #pragma unroll
            for (int i = 0; i < 8; i++) a[i] = as[(ty*8 + i)*16 + kk];   // broadcast
            *(float4*)&b[0] = *(const float4*)&bs[kk*128 + tx*8];
            *(float4*)&b[4] = *(const float4*)&bs[kk*128 + tx*8 + 4];
            #pragma unroll
            for (int i = 0; i < 8; i++)
                #pragma unroll
                for (int j = 0; j < 8; j++)
                    acc[i][j] += a[i]*b[j];
        }
        __syncthreads();
    }

    const int nb = n0 + tx*8;
    float bv[8];
    #pragma unroll
    for (int j = 0; j < 8; j++) bv[j] = bias[nb + j];

    if (SCATTER) {
        const int which = nb / Ed;
        const int hh    = (nb % Ed) >> 6;
        const int d0    = nb & 63;
        float* dst = (which == 0) ? g_Q : (which == 1) ? g_K : g_V;
        #pragma unroll
        for (int i = 0; i < 8; i++) {
            int m = m0 + ty*8 + i;
            int bb = m >> 10, ss = m & 1023;
            float* p = &dst[(size_t)((bb*Hh + hh)*Sq + ss)*Dd + d0];
            float4 v0, v1;
            v0.x = acc[i][0]+bv[0]; v0.y = acc[i][1]+bv[1];
            v0.z = acc[i][2]+bv[2]; v0.w = acc[i][3]+bv[3];
            v1.x = acc[i][4]+bv[4]; v1.y = acc[i][5]+bv[5];
            v1.z = acc[i][6]+bv[6]; v1.w = acc[i][7]+bv[7];
            *(float4*)p     = v0;
            *(float4*)(p+4) = v1;
        }
    } else {
        #pragma unroll
        for (int i = 0; i < 8; i++) {
            int m = m0 + ty*8 + i;
            float* p = &out[(size_t)m * NDIM + nb];
            float4 v0, v1;
            v0.x = acc[i][0]+bv[0]; v0.y = acc[i][1]+bv[1];
            v0.z = acc[i][2]+bv[2]; v0.w = acc[i][3]+bv[3];
            v1.x = acc[i][4]+bv[4]; v1.y = acc[i][5]+bv[5];
            v1.z = acc[i][6]+bv[6]; v1.w = acc[i][7]+bv[7];
            *(float4*)p     = v0;
            *(float4*)(p+4) = v1;
        }
    }
}

// ============================================================
// Fused attention: scores -> exact top-k threshold -> softmax
// -> PV.  One CTA per (b*h, 16 q-rows). 256 threads.
// cp.async double-buffered K/V tiles of 128 rows.
// ============================================================
__global__ __launch_bounds__(256) void attn_kernel() {
    extern __shared__ float sm[];
    float* q_s  = sm;                 // 16*64   = 1024
    float* sc   = sm + 1024;          // 16*1024 = 16384
    float* kv0  = sc + 16384;         // 128*68  = 8704
    float* kv1  = kv0 + 8704;         // 8704
    float* invs = kv1 + 8704;         // 16
    // total 34832 floats = 139328 B

    const int t  = threadIdx.x;
    const int bh = blockIdx.y;
    const int q0 = blockIdx.x * QT;
    const float* Qg = g_Q + (size_t)bh*Sq*Dd;
    const float* Kg = g_K + (size_t)bh*Sq*Dd;
    const float* Vg = g_V + (size_t)bh*Sq*Dd;

    auto issue_tile = [&](float* buf, const float* src, int kt0) {
        #pragma unroll
        for (int i = 0; i < 8; i++) {
            int f = t + 256*i;
            int row = f >> 4, c4 = (f & 15) << 2;
            cp16(&buf[row*KVP + c4], &src[(size_t)(kt0 + row)*Dd + c4]);
        }
        cp_commit();
    };

    // stage q tile (pre-scaled by head_dim^-0.5 = 0.125)
    {
        int r = t >> 4, c = (t & 15) << 2;
        float4 v = *(const float4*)&Qg[(size_t)(q0 + r)*Dd + c];
        v.x *= 0.125f; v.y *= 0.125f; v.z *= 0.125f; v.w *= 0.125f;
        *(float4*)&q_s[r*Dd + c] = v;
    }

    // ================= scores =================
    issue_tile(kv0, Kg, 0);
    {
        const int qg = t >> 6;    // q-group (4 rows)
        const int kg = t & 63;    // k within tile (rows kg, kg+64)
        for (int it = 0; it < 8; it++) {
            if (it < 7) { issue_tile((it & 1) ? kv0 : kv1, Kg, (it + 1)*KTT); cp_wait<1>(); }
            else        { cp_wait<0>(); }
            __syncthreads();
            const float* buf = (it & 1) ? kv1 : kv0;
            float a00=0.f,a01=0.f,a10=0.f,a11=0.f,a20=0.f,a21=0.f,a30=0.f,a31=0.f;
            #pragma unroll
            for (int c = 0; c < Dd; c += 4) {
                float4 k4 = *(const float4*)&buf[kg*KVP + c];
                float4 k5 = *(const float4*)&buf[(kg+64)*KVP + c];
                float4 q;
                q = *(const float4*)&q_s[(qg*4+0)*Dd + c];
                a00 += q.x*k4.x + q.y*k4.y + q.z*k4.z + q.w*k4.w;
                a01 += q.x*k5.x + q.y*k5.y + q.z*k5.z + q.w*k5.w;
                q = *(const float4*)&q_s[(qg*4+1)*Dd + c];
                a10 += q.x*k4.x + q.y*k4.y + q.z*k4.z + q.w*k4.w;
                a11 += q.x*k5.x + q.y*k5.y + q.z*k5.z + q.w*k5.w;
                q = *(const float4*)&q_s[(qg*4+2)*Dd + c];
                a20 += q.x*k4.x + q.y*k4.y + q.z*k4.z + q.w*k4.w;
                a21 += q.x*k5.x + q.y*k5.y + q.z*k5.z + q.w*k5.w;
                q = *(const float4*)&q_s[(qg*4+3)*Dd + c];
                a30 += q.x*k4.x + q.y*k4.y + q.z*k4.z + q.w*k4.w;
                a31 += q.x*k5.x + q.y*k5.y + q.z*k5.z + q.w*k5.w;
            }
            const int kb = it*KTT;
            sc[(qg*4+0)*Sq + kb + kg] = a00;  sc[(qg*4+0)*Sq + kb + kg + 64] = a01;
            sc[(qg*4+1)*Sq + kb + kg] = a10;  sc[(qg*4+1)*Sq + kb + kg + 64] = a11;
            sc[(qg*4+2)*Sq + kb + kg] = a20;  sc[(qg*4+2)*Sq + kb + kg + 64] = a21;
            sc[(qg*4+3)*Sq + kb + kg] = a30;  sc[(qg*4+3)*Sq + kb + kg + 64] = a31;
            __syncthreads();
        }
    }

    // prefetch V tile 0 now; it flies during top-k
    issue_tile(kv0, Vg, 0);

    // ====== exact top-k threshold + softmax in place ======
    {
        const int warp = t >> 5, lane = t & 31;
        for (int r = warp*2; r < warp*2 + 2; r++) {
            float* row = sc + r*Sq;
            unsigned u[32];
            float mx = -3.4e38f;
            #pragma unroll
            for (int i = 0; i < 32; i++) {
                float f = row[i*32 + lane];
                mx = fmaxf(mx, f);
                unsigned b = __float_as_uint(f);
                u[i] = b ^ (unsigned)(((int)b >> 31) | (int)0x80000000);
            }
            #pragma unroll
            for (int o = 16; o; o >>= 1) mx = fmaxf(mx, __shfl_xor_sync(0xffffffffu, mx, o));

            unsigned pref = 0;
            #pragma unroll 1
            for (int bb = 31; bb >= 0; bb--) {
                unsigned trial = pref | (1u << bb);
                int c = 0;
                #pragma unroll
                for (int i = 0; i < 32; i++) c += (u[i] >= trial) ? 1 : 0;
                c = (int)__reduce_add_sync(0xffffffffu, (unsigned)c);
                if (c >= TOPK) pref = trial;
            }

            float ssum = 0.f;
            #pragma unroll
            for (int i = 0; i < 32; i++) {
                float p = 0.f;
                if (u[i] >= pref) {
                    unsigned b = (u[i] & 0x80000000u) ? (u[i] ^ 0x80000000u) : ~u[i];
                    p = __expf(__uint_as_float(b) - mx);
                }
                ssum += p;
                row[i*32 + lane] = p;
            }
            #pragma unroll
            for (int o = 16; o; o >>= 1) ssum += __shfl_xor_sync(0xffffffffu, ssum, o);
            if (lane == 0) invs[r] = 1.f / ssum;
        }
    }
    __syncthreads();   // p values + invs visible to all

    // ================= PV =================
    // thread = (ks: k-split 0..3, qg2: 4 q-rows, dg: 4 d-cols)
    const int ks  = t >> 6;
    const int qg2 = (t >> 4) & 3;
    const int dg  = t & 15;
    float o[4][4];
    #pragma unroll
    for (int i = 0; i < 4; i++)
        #pragma unroll
        for (int j = 0; j < 4; j++) o[i][j] = 0.f;

    for (int it = 0; it < 8; it++) {
        if (it < 7) { issue_tile((it & 1) ? kv0 : kv1, Vg, (it + 1)*KTT); cp_wait<1>(); }
        else        { cp_wait<0>(); }
        __syncthreads();
        const float* buf = (it & 1) ? kv1 : kv0;
        const int kb = it*KTT + ks*32;
        #pragma unroll
        for (int kk = 0; kk < 32; kk += 4) {
            float4 v0 = *(const float4*)&buf[(ks*32 + kk + 0)*KVP + dg*4];
            float4 v1 = *(const float4*)&buf[(ks*32 + kk + 1)*KVP + dg*4];
            float4 v2 = *(const float4*)&buf[(ks*32 + kk + 2)*KVP + dg*4];
            float4 v3 = *(const float4*)&buf[(ks*32 + kk + 3)*KVP + dg*4];
            #pragma unroll
            for (int i = 0; i < 4; i++) {
                float4 p = *(const float4*)&sc[(qg2*4 + i)*Sq + kb + kk];
                o[i][0] += p.x*v0.x + p.y*v1.x + p.z*v2.x + p.w*v3.x;
                o[i][1] += p.x*v0.y + p.y*v1.y + p.z*v2.y + p.w*v3.y;
                o[i][2] += p.x*v0.z + p.y*v1.z + p.z*v2.z + p.w*v3.z;
                o[i][3] += p.x*v0.w + p.y*v1.w + p.z*v2.w + p.w*v3.w;
            }
        }
        __syncthreads();
    }

    // reduce across the 4 k-splits via smem (reuse kv0 area)
    float* red = kv0;   // 4*16*64 = 4096 floats
    #pragma unroll
    for (int i = 0; i < 4; i++)
        *(float4*)&red[ks*1024 + (qg2*4 + i)*64 + dg*4] = *(float4*)&o[i][0];
    __syncthreads();

    {
        const int q  = t >> 4;
        const int d0 = (t & 15) << 2;
        float4 s0 = *(const float4*)&red[0*1024 + t*4];
        float4 s1 = *(const float4*)&red[1*1024 + t*4];
        float4 s2 = *(const float4*)&red[2*1024 + t*4];
        float4 s3 = *(const float4*)&red[3*1024 + t*4];
        float iv = invs[q];
        float4 r;
        r.x = (s0.x + s1.x + s2.x + s3.x) * iv;
        r.y = (s0.y + s1.y + s2.y + s3.y) * iv;
        r.z = (s0.z + s1.z + s2.z + s3.z) * iv;
        r.w = (s0.w + s1.w + s2.w + s3.w) * iv;
        const int bb = bh / Hh, hh = bh % Hh;
        *(float4*)&g_AO[(size_t)((bb*Sq + q0 + q)*Hh + hh)*Dd + d0] = r;
    }
}

// ============================================================
// launch
// ============================================================
extern "C" void kernel_launch(void* const* d_in, const int* in_sizes, int n_in,
                              void* d_out, int out_size) {
    const float* hidden = (const float*)d_in[0];
    const float* Wqkv   = (const float*)d_in[1];
    const float* bqkv   = (const float*)d_in[2];
    const float* Wproj  = (const float*)d_in[3];
    const float* bproj  = (const float*)d_in[4];
    float* out = (float*)d_out;

    const int attn_smem = (1024 + 16384 + 2*8704 + 16) * (int)sizeof(float); // 139328
    cudaFuncSetAttribute(attn_kernel, cudaFuncAttributeMaxDynamicSharedMemorySize, attn_smem);

    gemm128<N3, true ><<<dim3(N3/128, (Bz*Sq)/128), 256>>>(hidden, Wqkv, bqkv, nullptr);
    attn_kernel<<<dim3(Sq/QT, Bz*Hh), 256, attn_smem>>>();
    gemm128<Ed, false><<<dim3(Ed/128, (Bz*Sq)/128), 256>>>(nullptr, Wproj, bproj, out);
}

// round 5
// speedup vs baseline: 1.2409x; 1.2409x over previous
#include <cuda_runtime.h>
#include <cstdint>

#define Bz 8
#define Sq 1024
#define Ed 768
#define Hh 12
#define Dd 64
#define N3 2304
#define TOPK 409
#define QT 16
#define KTT 128      // K/V rows per attn tile (single smem buffer + reg pipeline)
#define KVP 68       // padded row stride (words)

// ---- scratch (allocation-free rule: __device__ globals) ----
__device__ float g_Q[Bz*Hh*Sq*Dd];   // [b,h,s,d]
__device__ float g_K[Bz*Hh*Sq*Dd];
__device__ float g_V[Bz*Hh*Sq*Dd];
__device__ float g_AO[Bz*Sq*Ed];     // attention out, [b,s,h,d] = [8192, 768]

// ---- cp.async helpers ----
__device__ __forceinline__ void cp16(void* smem_dst, const void* gmem_src) {
    unsigned s = (unsigned)__cvta_generic_to_shared(smem_dst);
    asm volatile("cp.async.cg.shared.global [%0], [%1], 16;" :: "r"(s), "l"(gmem_src));
}
__device__ __forceinline__ void cp_commit() { asm volatile("cp.async.commit_group;"); }
template<int N>
__device__ __forceinline__ void cp_wait() { asm volatile("cp.async.wait_group %0;" :: "n"(N)); }

// ============================================================
// GEMM: out = A[M,768] @ W[768,NDIM] + bias. 128x128x16 tiles.
// A staged transposed [k][m] (stride 132) via LDG->regs->STS;
// B via cp.async. ONE __syncthreads per k-tile.
// ============================================================
#define ATS 132   // At row stride (words)

template<int NDIM, bool SCATTER>
__global__ __launch_bounds__(256, 2) void gemm128(const float* __restrict__ A_in,
                                                  const float* __restrict__ W,
                                                  const float* __restrict__ bias,
                                                  float* __restrict__ out) {
    // __device__ symbol must be resolved in device code, not host.
    const float* A = SCATTER ? A_in : (const float*)g_AO;

    __shared__ float At[2][16*ATS];   // [k][m]
    __shared__ float Bs[2][16*128];   // [k][n]
    const int t  = threadIdx.x;
    const int tx = t & 15, ty = t >> 4;
    const int m0 = blockIdx.y * 128, n0 = blockIdx.x * 128;
    const int am = t >> 2;            // 0..63 -> rows am, am+64
    const int ak = (t & 3) << 2;      // k offset

    float4 rA[2][2];
    auto ldgA = [&](int p, int kt) {
        rA[p][0] = *(const float4*)&A[(size_t)(m0 + am     )*Ed + kt*16 + ak];
        rA[p][1] = *(const float4*)&A[(size_t)(m0 + am + 64)*Ed + kt*16 + ak];
    };
    auto stsA = [&](int buf, int p) {
        #pragma unroll
        for (int j = 0; j < 4; j++) {
            At[buf][(ak+j)*ATS + am]      = ((const float*)&rA[p][0])[j];
            At[buf][(ak+j)*ATS + am + 64] = ((const float*)&rA[p][1])[j];
        }
    };
    auto issueB = [&](int buf, int kt) {
        #pragma unroll
        for (int i = 0; i < 2; i++) {
            int f = t + 256*i;
            int kr = f >> 5, nc = (f & 31) << 2;
            cp16(&Bs[buf][kr*128 + nc], &W[(size_t)(kt*16 + kr)*NDIM + n0 + nc]);
        }
        cp_commit();
    };

    float acc[8][8];
    #pragma unroll
    for (int i = 0; i < 8; i++)
        #pragma unroll
        for (int j = 0; j < 8; j++) acc[i][j] = 0.f;

    const int NT = Ed / 16;  // 48
    // prologue
    ldgA(0, 0); issueB(0, 0);
    stsA(0, 0);               // safe: nobody has read At yet
    ldgA(1, 1);

    for (int kt = 0; kt < NT; kt++) {
        cp_wait<0>();         // B(kt) landed (it had compute(kt-1) to fly)
        __syncthreads();      // At[kt&1] + Bs[kt&1] visible to all
        if (kt + 1 < NT) { issueB((kt+1)&1, kt+1); stsA((kt+1)&1, (kt+1)&1); }
        if (kt + 2 < NT) { ldgA(kt&1, kt+2); }

        const float* at = At[kt&1];
        const float* bs = Bs[kt&1];
        #pragma unroll
        for (int kk = 0; kk < 16; kk++) {
            float a[8], b[8];
            *(float4*)&a[0] = *(const float4*)&at[kk*ATS + ty*8];
            *(float4*)&a[4] = *(const float4*)&at[kk*ATS + ty*8 + 4];
            *(float4*)&b[0] = *(const float4*)&bs[kk*128 + tx*8];
            *(float4*)&b[4] = *(const float4*)&bs[kk*128 + tx*8 + 4];
            #pragma unroll
            for (int i = 0; i < 8; i++)
                #pragma unroll
                for (int j = 0; j < 8; j++)
                    acc[i][j] += a[i]*b[j];
        }
    }

    const int nb = n0 + tx*8;
    float bv[8];
    #pragma unroll
    for (int j = 0; j < 8; j++) bv[j] = bias[nb + j];

    if (SCATTER) {
        const int which = nb / Ed;
        const int hh    = (nb % Ed) >> 6;
        const int d0    = nb & 63;
        float* dst = (which == 0) ? g_Q : (which == 1) ? g_K : g_V;
        #pragma unroll
        for (int i = 0; i < 8; i++) {
            int m = m0 + ty*8 + i;
            int bb = m >> 10, ss = m & 1023;
            float* p = &dst[(size_t)((bb*Hh + hh)*Sq + ss)*Dd + d0];
            float4 v0, v1;
            v0.x = acc[i][0]+bv[0]; v0.y = acc[i][1]+bv[1];
            v0.z = acc[i][2]+bv[2]; v0.w = acc[i][3]+bv[3];
            v1.x = acc[i][4]+bv[4]; v1.y = acc[i][5]+bv[5];
            v1.z = acc[i][6]+bv[6]; v1.w = acc[i][7]+bv[7];
            *(float4*)p     = v0;
            *(float4*)(p+4) = v1;
        }
    } else {
        #pragma unroll
        for (int i = 0; i < 8; i++) {
            int m = m0 + ty*8 + i;
            float* p = &out[(size_t)m * NDIM + nb];
            float4 v0, v1;
            v0.x = acc[i][0]+bv[0]; v0.y = acc[i][1]+bv[1];
            v0.z = acc[i][2]+bv[2]; v0.w = acc[i][3]+bv[3];
            v1.x = acc[i][4]+bv[4]; v1.y = acc[i][5]+bv[5];
            v1.z = acc[i][6]+bv[6]; v1.w = acc[i][7]+bv[7];
            *(float4*)p     = v0;
            *(float4*)(p+4) = v1;
        }
    }
}

// ============================================================
// Fused attention. One CTA per (b*h, 16 q-rows). 256 threads.
// smem = 104.5KB -> 2 CTAs/SM. Single K/V tile in smem,
// next tile pipelined through registers (LDG early, STS late).
// ============================================================
__global__ __launch_bounds__(256, 2) void attn_kernel() {
    extern __shared__ float sm[];
    float* q_s  = sm;                 // 16*64   = 1024
    float* sc   = sm + 1024;          // 16*1024 = 16384
    float* kv   = sc + 16384;         // 128*68  = 8704
    float* invs = kv + 8704;          // 16
    // total 26128 floats = 104512 B

    const int t  = threadIdx.x;
    const int bh = blockIdx.y;
    const int q0 = blockIdx.x * QT;
    const float* Qg = g_Q + (size_t)bh*Sq*Dd;
    const float* Kg = g_K + (size_t)bh*Sq*Dd;
    const float* Vg = g_V + (size_t)bh*Sq*Dd;

    const int prow = t >> 4, pc4 = (t & 15) << 2;   // tile-staging coords
    float4 pf[8];
    auto ldg_tile = [&](const float* src, int kt0) {
        #pragma unroll
        for (int i = 0; i < 8; i++)
            pf[i] = *(const float4*)&src[(size_t)(kt0*KTT + prow + 16*i)*Dd + pc4];
    };
    auto sts_tile = [&]() {
        #pragma unroll
        for (int i = 0; i < 8; i++)
            *(float4*)&kv[(prow + 16*i)*KVP + pc4] = pf[i];
    };
    auto cp_tile = [&](const float* src, int kt0) {
        #pragma unroll
        for (int i = 0; i < 8; i++)
            cp16(&kv[(prow + 16*i)*KVP + pc4], &src[(size_t)(kt0*KTT + prow + 16*i)*Dd + pc4]);
        cp_commit();
    };

    // stage q tile (pre-scaled by head_dim^-0.5 = 0.125)
    {
        float4 v = *(const float4*)&Qg[(size_t)(q0 + prow)*Dd + pc4];
        v.x *= 0.125f; v.y *= 0.125f; v.z *= 0.125f; v.w *= 0.125f;
        *(float4*)&q_s[prow*Dd + pc4] = v;
    }

    // ================= scores =================
    cp_tile(Kg, 0);
    ldg_tile(Kg, 1);
    cp_wait<0>(); __syncthreads();

    const int qg = t >> 6;    // q-group: rows qg, qg+4, qg+8, qg+12
    const int kg = t & 63;    // keys kg, kg+64 within tile
    for (int it = 0; it < 8; it++) {
        float a00=0.f,a01=0.f,a10=0.f,a11=0.f,a20=0.f,a21=0.f,a30=0.f,a31=0.f;
        #pragma unroll
        for (int c = 0; c < Dd; c += 4) {
            float4 k4 = *(const float4*)&kv[kg*KVP + c];
            float4 k5 = *(const float4*)&kv[(kg+64)*KVP + c];
            float4 q;
            q = *(const float4*)&q_s[(qg+ 0)*Dd + c];
            a00 += q.x*k4.x + q.y*k4.y + q.z*k4.z + q.w*k4.w;
            a01 += q.x*k5.x + q.y*k5.y + q.z*k5.z + q.w*k5.w;
            q = *(const float4*)&q_s[(qg+ 4)*Dd + c];
            a10 += q.x*k4.x + q.y*k4.y + q.z*k4.z + q.w*k4.w;
            a11 += q.x*k5.x + q.y*k5.y + q.z*k5.z + q.w*k5.w;
            q = *(const float4*)&q_s[(qg+ 8)*Dd + c];
            a20 += q.x*k4.x + q.y*k4.y + q.z*k4.z + q.w*k4.w;
            a21 += q.x*k5.x + q.y*k5.y + q.z*k5.z + q.w*k5.w;
            q = *(const float4*)&q_s[(qg+12)*Dd + c];
            a30 += q.x*k4.x + q.y*k4.y + q.z*k4.z + q.w*k4.w;
            a31 += q.x*k5.x + q.y*k5.y + q.z*k5.z + q.w*k5.w;
        }
        const int kb = it*KTT;
        sc[(qg+ 0)*Sq + kb + kg] = a00;  sc[(qg+ 0)*Sq + kb + kg + 64] = a01;
        sc[(qg+ 4)*Sq + kb + kg] = a10;  sc[(qg+ 4)*Sq + kb + kg + 64] = a11;
        sc[(qg+ 8)*Sq + kb + kg] = a20;  sc[(qg+ 8)*Sq + kb + kg + 64] = a21;
        sc[(qg+12)*Sq + kb + kg] = a30;  sc[(qg+12)*Sq + kb + kg + 64] = a31;
        __syncthreads();                     // all readers done with kv
        if (it < 7) {
            sts_tile();                      // K tile it+1 -> smem
            if (it < 6) ldg_tile(Kg, it+2);  // hides under compute(it+1)
            __syncthreads();
        }
    }
    __syncthreads();

    // V tile 0 flies (async, no regs) while top-k runs
    cp_tile(Vg, 0);

    // ====== exact top-k threshold + softmax in place ======
    {
        const int warp = t >> 5, lane = t & 31;
        for (int r = warp*2; r < warp*2 + 2; r++) {
            float* row = sc + r*Sq;
            unsigned u[32];
            float mx = -3.4e38f;
            #pragma unroll
            for (int i = 0; i < 32; i++) {
                float f = row[i*32 + lane];
                mx = fmaxf(mx, f);
                unsigned b = __float_as_uint(f);
                u[i] = b ^ (unsigned)(((int)b >> 31) | (int)0x80000000);
            }
            #pragma unroll
            for (int o = 16; o; o >>= 1) mx = fmaxf(mx, __shfl_xor_sync(0xffffffffu, mx, o));

            unsigned pref = 0;
            #pragma unroll 1
            for (int bb = 31; bb >= 0; bb--) {
                unsigned trial = pref | (1u << bb);
                int c = 0;
                #pragma unroll
                for (int i = 0; i < 32; i++) c += (u[i] >= trial) ? 1 : 0;
                c = (int)__reduce_add_sync(0xffffffffu, (unsigned)c);
                if (c >= TOPK) pref = trial;
            }

            float ssum = 0.f;
            #pragma unroll
            for (int i = 0; i < 32; i++) {
                float p = 0.f;
                if (u[i] >= pref) {
                    unsigned b = (u[i] & 0x80000000u) ? (u[i] ^ 0x80000000u) : ~u[i];
                    p = __expf(__uint_as_float(b) - mx);
                }
                ssum += p;
                row[i*32 + lane] = p;
            }
            #pragma unroll
            for (int o = 16; o; o >>= 1) ssum += __shfl_xor_sync(0xffffffffu, ssum, o);
            if (lane == 0) invs[r] = 1.f / ssum;
        }
    }

    ldg_tile(Vg, 1);
    cp_wait<0>(); __syncthreads();   // V0 in smem, p + invs visible

    // ================= PV =================
    const int ks  = t >> 6;          // k-split 0..3
    const int qg2 = (t >> 4) & 3;    // 4 q-rows
    const int dg  = t & 15;          // 4 d-cols
    float o[4][4];
    #pragma unroll
    for (int i = 0; i < 4; i++)
        #pragma unroll
        for (int j = 0; j < 4; j++) o[i][j] = 0.f;

    for (int it = 0; it < 8; it++) {
        const int kb = it*KTT + ks*32;
        #pragma unroll
        for (int kk = 0; kk < 32; kk += 4) {
            float4 v0 = *(const float4*)&kv[(ks*32 + kk + 0)*KVP + dg*4];
            float4 v1 = *(const float4*)&kv[(ks*32 + kk + 1)*KVP + dg*4];
            float4 v2 = *(const float4*)&kv[(ks*32 + kk + 2)*KVP + dg*4];
            float4 v3 = *(const float4*)&kv[(ks*32 + kk + 3)*KVP + dg*4];
            #pragma unroll
            for (int i = 0; i < 4; i++) {
                float4 p = *(const float4*)&sc[(qg2*4 + i)*Sq + kb + kk];
                o[i][0] += p.x*v0.x + p.y*v1.x + p.z*v2.x + p.w*v3.x;
                o[i][1] += p.x*v0.y + p.y*v1.y + p.z*v2.y + p.w*v3.y;
                o[i][2] += p.x*v0.z + p.y*v1.z + p.z*v2.z + p.w*v3.z;
                o[i][3] += p.x*v0.w + p.y*v1.w + p.z*v2.w + p.w*v3.w;
            }
        }
        __syncthreads();
        if (it < 7) {
            sts_tile();                      // V tile it+1
            if (it < 6) ldg_tile(Vg, it+2);
            __syncthreads();
        }
    }

    // reduce across the 4 k-splits (reuse kv area)
    float* red = kv;   // 4096 floats
    #pragma unroll
    for (int i = 0; i < 4; i++)
        *(float4*)&red[ks*1024 + (qg2*4 + i)*64 + dg*4] = *(float4*)&o[i][0];
    __syncthreads();

    {
        const int q  = t >> 4;
        float4 s0 = *(const float4*)&red[0*1024 + t*4];
        float4 s1 = *(const float4*)&red[1*1024 + t*4];
        float4 s2 = *(const float4*)&red[2*1024 + t*4];
        float4 s3 = *(const float4*)&red[3*1024 + t*4];
        float iv = invs[q];
        float4 r;
        r.x = (s0.x + s1.x + s2.x + s3.x) * iv;
        r.y = (s0.y + s1.y + s2.y + s3.y) * iv;
        r.z = (s0.z + s1.z + s2.z + s3.z) * iv;
        r.w = (s0.w + s1.w + s2.w + s3.w) * iv;
        const int bb = bh / Hh, hh = bh % Hh;
        *(float4*)&g_AO[(size_t)((bb*Sq + q0 + q)*Hh + hh)*Dd + ((t & 15) << 2)] = r;
    }
}

// ============================================================
// launch
// ============================================================
extern "C" void kernel_launch(void* const* d_in, const int* in_sizes, int n_in,
                              void* d_out, int out_size) {
    const float* hidden = (const float*)d_in[0];
    const float* Wqkv   = (const float*)d_in[1];
    const float* bqkv   = (const float*)d_in[2];
    const float* Wproj  = (const float*)d_in[3];
    const float* bproj  = (const float*)d_in[4];
    float* out = (float*)d_out;

    const int attn_smem = (1024 + 16384 + 8704 + 16) * (int)sizeof(float); // 104512
    cudaFuncSetAttribute(attn_kernel, cudaFuncAttributeMaxDynamicSharedMemorySize, attn_smem);

    gemm128<N3, true ><<<dim3(N3/128, (Bz*Sq)/128), 256>>>(hidden, Wqkv, bqkv, nullptr);
    attn_kernel<<<dim3(Sq/QT, Bz*Hh), 256, attn_smem>>>();
    gemm128<Ed, false><<<dim3(Ed/128, (Bz*Sq)/128), 256>>>(nullptr, Wproj, bproj, out);
}

// round 7
// speedup vs baseline: 1.4101x; 1.1363x over previous
#include <cuda_runtime.h>
#include <cstdint>

#define Bz 8
#define Sq 1024
#define Ed 768
#define Hh 12
#define Dd 64
#define N3 2304
#define TOPK 409
#define QT 16
#define KTT 128
#define KVP 68

#define ASTR 20    // A smem row stride (words)
#define BSTR 136   // B smem row stride (words)

// ---- scratch (allocation-free rule: __device__ globals) ----
__device__ float g_Q[Bz*Hh*Sq*Dd];
__device__ float g_K[Bz*Hh*Sq*Dd];
__device__ float g_V[Bz*Hh*Sq*Dd];
__device__ float g_AO[Bz*Sq*Ed];     // [b,s,h,d] = [8192, 768]

// ---- cp.async helpers ----
__device__ __forceinline__ void cp16(void* smem_dst, const void* gmem_src) {
    unsigned s = (unsigned)__cvta_generic_to_shared(smem_dst);
    asm volatile("cp.async.cg.shared.global [%0], [%1], 16;" :: "r"(s), "l"(gmem_src));
}
__device__ __forceinline__ void cp_commit() { asm volatile("cp.async.commit_group;"); }
template<int N>
__device__ __forceinline__ void cp_wait() { asm volatile("cp.async.wait_group %0;" :: "n"(N)); }

// ---- 3xTF32 helpers ----
__device__ __forceinline__ void split_tf32(float x, uint32_t& hi, uint32_t& lo) {
    uint32_t h;
    asm("cvt.rna.tf32.f32 %0, %1;" : "=r"(h) : "f"(x));
    float l = x - __uint_as_float(h);
    uint32_t lw;
    asm("cvt.rna.tf32.f32 %0, %1;" : "=r"(lw) : "f"(l));
    hi = h; lo = lw;
}
__device__ __forceinline__ void mma_tf32(float4& d, const uint32_t a[4], const uint32_t b[2]) {
    asm volatile("mma.sync.aligned.m16n8k8.row.col.f32.tf32.tf32.f32 "
                 "{%0,%1,%2,%3}, {%4,%5,%6,%7}, {%8,%9}, {%0,%1,%2,%3};"
                 : "+f"(d.x), "+f"(d.y), "+f"(d.z), "+f"(d.w)
                 : "r"(a[0]), "r"(a[1]), "r"(a[2]), "r"(a[3]), "r"(b[0]), "r"(b[1]));
}

// ============================================================
// 3xTF32 GEMM: out = A[M,768] @ W[768,NDIM] + bias (fp32-accurate)
// CTA 128x128x16, 8 warps (2x4), warp tile 64x32 via m16n8k8.
// ============================================================
template<int NDIM, bool SCATTER>
__global__ __launch_bounds__(256, 2) void gemm_tf32(const float* __restrict__ A_in,
                                                    const float* __restrict__ W,
                                                    const float* __restrict__ bias,
                                                    float* __restrict__ out) {
    // __device__ symbol must be resolved in device code, not host.
    const float* A = SCATTER ? A_in : (const float*)g_AO;

    __shared__ float As[2][128*ASTR];   // [m][k]
    __shared__ float Bs[2][16*BSTR];    // [k][n]

    const int t    = threadIdx.x;
    const int warp = t >> 5, lane = t & 31;
    const int gid  = lane >> 2, tig = lane & 3;
    const int m0   = blockIdx.y * 128, n0 = blockIdx.x * 128;
    const int wm   = (warp >> 2) * 64;
    const int wn   = (warp & 3) * 32;

    auto issue = [&](int buf, int kt) {
        #pragma unroll
        for (int i = 0; i < 2; i++) {               // A tile 128x16
            int f = t + 256*i;
            int m = f >> 2, kc = (f & 3) << 2;
            cp16(&As[buf][m*ASTR + kc], &A[(size_t)(m0 + m)*Ed + kt*16 + kc]);
        }
        #pragma unroll
        for (int i = 0; i < 2; i++) {               // B tile 16x128
            int f = t + 256*i;
            int kr = f >> 5, nc = (f & 31) << 2;
            cp16(&Bs[buf][kr*BSTR + nc], &W[(size_t)(kt*16 + kr)*NDIM + n0 + nc]);
        }
        cp_commit();
    };

    float4 acc[4][4];
    #pragma unroll
    for (int i = 0; i < 4; i++)
        #pragma unroll
        for (int j = 0; j < 4; j++) acc[i][j] = make_float4(0.f, 0.f, 0.f, 0.f);

    issue(0, 0);
    const int NT = Ed / 16;  // 48
    for (int kt = 0; kt < NT; kt++) {
        if (kt + 1 < NT) { issue((kt + 1) & 1, kt + 1); cp_wait<1>(); }
        else             { cp_wait<0>(); }
        __syncthreads();
        const float* as = As[kt & 1];
        const float* bs = Bs[kt & 1];
        #pragma unroll
        for (int ko = 0; ko < 16; ko += 8) {
            uint32_t Bhi[4][2], Blo[4][2];
            #pragma unroll
            for (int j = 0; j < 4; j++) {
                const int nc = wn + 8*j + gid;
                split_tf32(bs[(ko + tig    )*BSTR + nc], Bhi[j][0], Blo[j][0]);
                split_tf32(bs[(ko + tig + 4)*BSTR + nc], Bhi[j][1], Blo[j][1]);
            }
            #pragma unroll
            for (int i = 0; i < 4; i++) {
                const int r0 = wm + 16*i + gid;
                uint32_t Ahi[4], Alo[4];
                split_tf32(as[ r0     *ASTR + ko + tig    ], Ahi[0], Alo[0]);
                split_tf32(as[(r0 + 8)*ASTR + ko + tig    ], Ahi[1], Alo[1]);
                split_tf32(as[ r0     *ASTR + ko + tig + 4], Ahi[2], Alo[2]);
                split_tf32(as[(r0 + 8)*ASTR + ko + tig + 4], Ahi[3], Alo[3]);
                #pragma unroll
                for (int j = 0; j < 4; j++) {
                    mma_tf32(acc[i][j], Alo, Bhi[j]);   // lo*hi
                    mma_tf32(acc[i][j], Ahi, Blo[j]);   // hi*lo
                    mma_tf32(acc[i][j], Ahi, Bhi[j]);   // hi*hi (last: largest term)
                }
            }
        }
        __syncthreads();
    }

    // ---- epilogue ----
    #pragma unroll
    for (int i = 0; i < 4; i++) {
        const int ma = m0 + wm + 16*i + gid;
        const int mb = ma + 8;
        #pragma unroll
        for (int j = 0; j < 4; j++) {
            const int nb = n0 + wn + 8*j + 2*tig;
            const float2 bv = *(const float2*)&bias[nb];
            float2 va = make_float2(acc[i][j].x + bv.x, acc[i][j].y + bv.y);
            float2 vb = make_float2(acc[i][j].z + bv.x, acc[i][j].w + bv.y);
            if (SCATTER) {
                const int which = nb / Ed;
                const int hh    = (nb % Ed) >> 6;
                const int d0    = nb & 63;
                float* dst = (which == 0) ? g_Q : (which == 1) ? g_K : g_V;
                {
                    int bb = ma >> 10, ss = ma & 1023;
                    *(float2*)&dst[(size_t)((bb*Hh + hh)*Sq + ss)*Dd + d0] = va;
                }
                {
                    int bb = mb >> 10, ss = mb & 1023;
                    *(float2*)&dst[(size_t)((bb*Hh + hh)*Sq + ss)*Dd + d0] = vb;
                }
            } else {
                *(float2*)&out[(size_t)ma * NDIM + nb] = va;
                *(float2*)&out[(size_t)mb * NDIM + nb] = vb;
            }
        }
    }
}

// ============================================================
// Fused attention (unchanged from R5 — passing at rel_err 1.8e-4)
// ============================================================
__global__ __launch_bounds__(256, 2) void attn_kernel() {
    extern __shared__ float sm[];
    float* q_s  = sm;                 // 1024
    float* sc   = sm + 1024;          // 16384
    float* kv   = sc + 16384;         // 8704
    float* invs = kv + 8704;          // 16

    const int t  = threadIdx.x;
    const int bh = blockIdx.y;
    const int q0 = blockIdx.x * QT;
    const float* Qg = g_Q + (size_t)bh*Sq*Dd;
    const float* Kg = g_K + (size_t)bh*Sq*Dd;
    const float* Vg = g_V + (size_t)bh*Sq*Dd;

    const int prow = t >> 4, pc4 = (t & 15) << 2;
    float4 pf[8];
    auto ldg_tile = [&](const float* src, int kt0) {
        #pragma unroll
        for (int i = 0; i < 8; i++)
            pf[i] = *(const float4*)&src[(size_t)(kt0*KTT + prow + 16*i)*Dd + pc4];
    };
    auto sts_tile = [&]() {
        #pragma unroll
        for (int i = 0; i < 8; i++)
            *(float4*)&kv[(prow + 16*i)*KVP + pc4] = pf[i];
    };
    auto cp_tile = [&](const float* src, int kt0) {
        #pragma unroll
        for (int i = 0; i < 8; i++)
            cp16(&kv[(prow + 16*i)*KVP + pc4], &src[(size_t)(kt0*KTT + prow + 16*i)*Dd + pc4]);
        cp_commit();
    };

    {
        float4 v = *(const float4*)&Qg[(size_t)(q0 + prow)*Dd + pc4];
        v.x *= 0.125f; v.y *= 0.125f; v.z *= 0.125f; v.w *= 0.125f;
        *(float4*)&q_s[prow*Dd + pc4] = v;
    }

    // ================= scores =================
    cp_tile(Kg, 0);
    ldg_tile(Kg, 1);
    cp_wait<0>(); __syncthreads();

    const int qg = t >> 6;
    const int kg = t & 63;
    for (int it = 0; it < 8; it++) {
        float a00=0.f,a01=0.f,a10=0.f,a11=0.f,a20=0.f,a21=0.f,a30=0.f,a31=0.f;
        #pragma unroll
        for (int c = 0; c < Dd; c += 4) {
            float4 k4 = *(const float4*)&kv[kg*KVP + c];
            float4 k5 = *(const float4*)&kv[(kg+64)*KVP + c];
            float4 q;
            q = *(const float4*)&q_s[(qg+ 0)*Dd + c];
            a00 += q.x*k4.x + q.y*k4.y + q.z*k4.z + q.w*k4.w;
            a01 += q.x*k5.x + q.y*k5.y + q.z*k5.z + q.w*k5.w;
            q = *(const float4*)&q_s[(qg+ 4)*Dd + c];
            a10 += q.x*k4.x + q.y*k4.y + q.z*k4.z + q.w*k4.w;
            a11 += q.x*k5.x + q.y*k5.y + q.z*k5.z + q.w*k5.w;
            q = *(const float4*)&q_s[(qg+ 8)*Dd + c];
            a20 += q.x*k4.x + q.y*k4.y + q.z*k4.z + q.w*k4.w;
            a21 += q.x*k5.x + q.y*k5.y + q.z*k5.z + q.w*k5.w;
            q = *(const float4*)&q_s[(qg+12)*Dd + c];
            a30 += q.x*k4.x + q.y*k4.y + q.z*k4.z + q.w*k4.w;
            a31 += q.x*k5.x + q.y*k5.y + q.z*k5.z + q.w*k5.w;
        }
        const int kb = it*KTT;
        sc[(qg+ 0)*Sq + kb + kg] = a00;  sc[(qg+ 0)*Sq + kb + kg + 64] = a01;
        sc[(qg+ 4)*Sq + kb + kg] = a10;  sc[(qg+ 4)*Sq + kb + kg + 64] = a11;
        sc[(qg+ 8)*Sq + kb + kg] = a20;  sc[(qg+ 8)*Sq + kb + kg + 64] = a21;
        sc[(qg+12)*Sq + kb + kg] = a30;  sc[(qg+12)*Sq + kb + kg + 64] = a31;
        __syncthreads();
        if (it < 7) {
            sts_tile();
            if (it < 6) ldg_tile(Kg, it+2);
            __syncthreads();
        }
    }
    __syncthreads();

    cp_tile(Vg, 0);   // V0 flies during top-k

    // ====== exact top-k threshold + softmax in place ======
    {
        const int warp = t >> 5, lane = t & 31;
        for (int r = warp*2; r < warp*2 + 2; r++) {
            float* row = sc + r*Sq;
            unsigned u[32];
            float mx = -3.4e38f;
            #pragma unroll
            for (int i = 0; i < 32; i++) {
                float f = row[i*32 + lane];
                mx = fmaxf(mx, f);
                unsigned b = __float_as_uint(f);
                u[i] = b ^ (unsigned)(((int)b >> 31) | (int)0x80000000);
            }
            #pragma unroll
            for (int o = 16; o; o >>= 1) mx = fmaxf(mx, __shfl_xor_sync(0xffffffffu, mx, o));

            unsigned pref = 0;
            #pragma unroll 1
            for (int bb = 31; bb >= 0; bb--) {
                unsigned trial = pref | (1u << bb);
                int c = 0;
                #pragma unroll
                for (int i = 0; i < 32; i++) c += (u[i] >= trial) ? 1 : 0;
                c = (int)__reduce_add_sync(0xffffffffu, (unsigned)c);
                if (c >= TOPK) pref = trial;
            }

            float ssum = 0.f;
            #pragma unroll
            for (int i = 0; i < 32; i++) {
                float p = 0.f;
                if (u[i] >= pref) {
                    unsigned b = (u[i] & 0x80000000u) ? (u[i] ^ 0x80000000u) : ~u[i];
                    p = __expf(__uint_as_float(b) - mx);
                }
                ssum += p;
                row[i*32 + lane] = p;
            }
            #pragma unroll
            for (int o = 16; o; o >>= 1) ssum += __shfl_xor_sync(0xffffffffu, ssum, o);
            if (lane == 0) invs[r] = 1.f / ssum;
        }
    }

    ldg_tile(Vg, 1);
    cp_wait<0>(); __syncthreads();

    // ================= PV =================
    const int ks  = t >> 6;
    const int qg2 = (t >> 4) & 3;
    const int dg  = t & 15;
    float o[4][4];
    #pragma unroll
    for (int i = 0; i < 4; i++)
        #pragma unroll
        for (int j = 0; j < 4; j++) o[i][j] = 0.f;

    for (int it = 0; it < 8; it++) {
        const int kb = it*KTT + ks*32;
        #pragma unroll
        for (int kk = 0; kk < 32; kk += 4) {
            float4 v0 = *(const float4*)&kv[(ks*32 + kk + 0)*KVP + dg*4];
            float4 v1 = *(const float4*)&kv[(ks*32 + kk + 1)*KVP + dg*4];
            float4 v2 = *(const float4*)&kv[(ks*32 + kk + 2)*KVP + dg*4];
            float4 v3 = *(const float4*)&kv[(ks*32 + kk + 3)*KVP + dg*4];
            #pragma unroll
            for (int i = 0; i < 4; i++) {
                float4 p = *(const float4*)&sc[(qg2*4 + i)*Sq + kb + kk];
                o[i][0] += p.x*v0.x + p.y*v1.x + p.z*v2.x + p.w*v3.x;
                o[i][1] += p.x*v0.y + p.y*v1.y + p.z*v2.y + p.w*v3.y;
                o[i][2] += p.x*v0.z + p.y*v1.z + p.z*v2.z + p.w*v3.z;
                o[i][3] += p.x*v0.w + p.y*v1.w + p.z*v2.w + p.w*v3.w;
            }
        }
        __syncthreads();
        if (it < 7) {
            sts_tile();
            if (it < 6) ldg_tile(Vg, it+2);
            __syncthreads();
        }
    }

    float* red = kv;
    #pragma unroll
    for (int i = 0; i < 4; i++)
        *(float4*)&red[ks*1024 + (qg2*4 + i)*64 + dg*4] = *(float4*)&o[i][0];
    __syncthreads();

    {
        const int q = t >> 4;
        float4 s0 = *(const float4*)&red[0*1024 + t*4];
        float4 s1 = *(const float4*)&red[1*1024 + t*4];
        float4 s2 = *(const float4*)&red[2*1024 + t*4];
        float4 s3 = *(const float4*)&red[3*1024 + t*4];
        float iv = invs[q];
        float4 r;
        r.x = (s0.x + s1.x + s2.x + s3.x) * iv;
        r.y = (s0.y + s1.y + s2.y + s3.y) * iv;
        r.z = (s0.z + s1.z + s2.z + s3.z) * iv;
        r.w = (s0.w + s1.w + s2.w + s3.w) * iv;
        const int bb = bh / Hh, hh = bh % Hh;
        *(float4*)&g_AO[(size_t)((bb*Sq + q0 + q)*Hh + hh)*Dd + ((t & 15) << 2)] = r;
    }
}

// ============================================================
// launch
// ============================================================
extern "C" void kernel_launch(void* const* d_in, const int* in_sizes, int n_in,
                              void* d_out, int out_size) {
    const float* hidden = (const float*)d_in[0];
    const float* Wqkv   = (const float*)d_in[1];
    const float* bqkv   = (const float*)d_in[2];
    const float* Wproj  = (const float*)d_in[3];
    const float* bproj  = (const float*)d_in[4];
    float* out = (float*)d_out;

    const int attn_smem = (1024 + 16384 + 8704 + 16) * (int)sizeof(float); // 104512
    cudaFuncSetAttribute(attn_kernel, cudaFuncAttributeMaxDynamicSharedMemorySize, attn_smem);

    gemm_tf32<N3, true ><<<dim3(N3/128, (Bz*Sq)/128), 256>>>(hidden, Wqkv, bqkv, nullptr);
    attn_kernel<<<dim3(Sq/QT, Bz*Hh), 256, attn_smem>>>();
    gemm_tf32<Ed, false><<<dim3(Ed/128, (Bz*Sq)/128), 256>>>(nullptr, Wproj, bproj, out);
}